// round 3
// baseline (speedup 1.0000x reference)
#include <cuda_runtime.h>
#include <math.h>

// Problem constants
#define HID   1024
#define NB    256
#define L_SEQ 512
#define NH    (NB * HID)      // 262144
#define NBLK  128             // persistent blocks (<= 148 SMs -> co-resident)
#define NTHR  256

// ---------------------------------------------------------------------------
// Device-global scratch (no allocation anywhere)
// ---------------------------------------------------------------------------
__device__ float g_h0a[NH], g_h0b[NH];   // layer-0 h ping-pong
__device__ float g_h1a[NH], g_h1b[NH];   // layer-1 h ping-pong
__device__ float g_c0[NH],  g_c1[NH];    // cell states
__device__ unsigned g_count = 0;         // barrier arrival counter
__device__ unsigned g_gen   = 0;         // barrier generation

__device__ __forceinline__ float sigm(float x) { return 1.0f / (1.0f + __expf(-x)); }

// Software grid barrier: valid because all NBLK blocks are co-resident.
__device__ __forceinline__ void grid_sync()
{
    __syncthreads();
    if (threadIdx.x == 0) {
        __threadfence();
        unsigned g = *(volatile unsigned*)&g_gen;
        if (atomicAdd(&g_count, 1u) == NBLK - 1) {
            g_count = 0;
            __threadfence();
            atomicAdd(&g_gen, 1u);
        } else {
            while (*(volatile unsigned*)&g_gen == g) { }
        }
        __threadfence();
    }
    __syncthreads();
}

// ---------------------------------------------------------------------------
// 128(m) x 64(n) tile GEMM-accumulate over K=1024, NT form:
//   acc[i][g] += sum_k A[mb+m][k] * W[wrow(g,u)][k]
// Thread microtile: 8 m-rows x 4 gate-columns (same hidden unit u).
// Software-pipelined: next chunk's global loads issued before current compute.
// ---------------------------------------------------------------------------
__device__ __forceinline__ void gemm1024(
    const float* __restrict__ A,      // pre-offset to batch row mb (row-major, 1024)
    const float* __restrict__ Wr,     // pre-offset to this loader thread's W row
    float (&acc)[8][4],
    float (*As)[128], float (*Bs)[64],
    int lm, int lk4, int lc, int lkb, int m0, int u)
{
    const float* Ap = A + lm * HID + lk4;
    const float* Bp = Wr + lkb;

    float4 av0 = *(const float4*)(Ap);
    float4 av1 = *(const float4*)(Ap + 8);
    float4 bv  = *(const float4*)(Bp);

    #pragma unroll 1
    for (int k0 = 0; k0 < HID; k0 += 16) {
        __syncthreads();                       // previous tile fully consumed
        As[lk4 + 0][lm] = av0.x; As[lk4 + 1][lm] = av0.y;
        As[lk4 + 2][lm] = av0.z; As[lk4 + 3][lm] = av0.w;
        As[lk4 + 8][lm] = av1.x; As[lk4 + 9][lm] = av1.y;
        As[lk4 +10][lm] = av1.z; As[lk4 +11][lm] = av1.w;
        Bs[lkb + 0][lc] = bv.x;  Bs[lkb + 1][lc] = bv.y;
        Bs[lkb + 2][lc] = bv.z;  Bs[lkb + 3][lc] = bv.w;
        __syncthreads();

        if (k0 + 16 < HID) {                   // prefetch next chunk
            av0 = *(const float4*)(Ap + k0 + 16);
            av1 = *(const float4*)(Ap + k0 + 24);
            bv  = *(const float4*)(Bp + k0 + 16);
        }

        #pragma unroll
        for (int kk = 0; kk < 16; ++kk) {
            float4 a0 = *(const float4*)&As[kk][m0];
            float4 a1 = *(const float4*)&As[kk][m0 + 4];
            float b0 = Bs[kk][u];
            float b1 = Bs[kk][16 + u];
            float b2 = Bs[kk][32 + u];
            float b3 = Bs[kk][48 + u];
            acc[0][0] += a0.x * b0; acc[0][1] += a0.x * b1; acc[0][2] += a0.x * b2; acc[0][3] += a0.x * b3;
            acc[1][0] += a0.y * b0; acc[1][1] += a0.y * b1; acc[1][2] += a0.y * b2; acc[1][3] += a0.y * b3;
            acc[2][0] += a0.z * b0; acc[2][1] += a0.z * b1; acc[2][2] += a0.z * b2; acc[2][3] += a0.z * b3;
            acc[3][0] += a0.w * b0; acc[3][1] += a0.w * b1; acc[3][2] += a0.w * b2; acc[3][3] += a0.w * b3;
            acc[4][0] += a1.x * b0; acc[4][1] += a1.x * b1; acc[4][2] += a1.x * b2; acc[4][3] += a1.x * b3;
            acc[5][0] += a1.y * b0; acc[5][1] += a1.y * b1; acc[5][2] += a1.y * b2; acc[5][3] += a1.y * b3;
            acc[6][0] += a1.z * b0; acc[6][1] += a1.z * b1; acc[6][2] += a1.z * b2; acc[6][3] += a1.z * b3;
            acc[7][0] += a1.w * b0; acc[7][1] += a1.w * b1; acc[7][2] += a1.w * b2; acc[7][3] += a1.w * b3;
        }
    }
}

// ---------------------------------------------------------------------------
// One persistent kernel: zero-init, 512 x (layer0 step, layer1 step), linear.
// Block b owns batch rows [ (b&1)*128, +128 ) and hidden units [ (b>>1)*16, +16 )
// (x all 4 gates). Same ownership every step -> cell state is block-private.
// ---------------------------------------------------------------------------
__global__ void __launch_bounds__(NTHR, 1) lstm_persist(
    const float* __restrict__ seq,
    const float* __restrict__ Wih0, const float* __restrict__ Whh0,
    const float* __restrict__ bih0, const float* __restrict__ bhh0,
    const float* __restrict__ Wih1, const float* __restrict__ Whh1,
    const float* __restrict__ bih1, const float* __restrict__ bhh1,
    const float* __restrict__ linW, const float* __restrict__ linb,
    float* __restrict__ out)
{
    __shared__ float As[16][128];
    __shared__ float Bs[16][64];
    __shared__ float Xs[128][8];     // layer-0 x tile (6 used, padded)
    __shared__ float Ws6[64][8];     // layer-0 Wih tile (6 used, padded)
    __shared__ float red[8];

    const int tid = threadIdx.x;
    const int bid = blockIdx.x;
    const int mb  = (bid & 1) * 128;       // batch base
    const int ub  = (bid >> 1) * 16;       // hidden-unit base

    const int u   = tid & 15;              // unit within tile
    const int m0  = (tid >> 4) * 8;        // first of 8 batch rows

    // loader lane mappings
    const int lm  = tid & 127;             // A tile row
    const int lk4 = (tid >> 7) * 4;        // A tile k offset {0,4}
    const int lc  = tid & 63;              // B tile col (gate*16 + unit)
    const int lkb = (tid >> 6) * 4;        // B tile k offset {0,4,8,12}
    const int wofs = ((lc >> 4) * HID + ub + (lc & 15)) * HID;  // loader's W row offset

    // biases held in registers for the whole run
    float bias0[4], bias1[4];
    #pragma unroll
    for (int gg = 0; gg < 4; ++gg) {
        int r = gg * HID + ub + u;
        bias0[gg] = bih0[r] + bhh0[r];
        bias1[gg] = bih1[r] + bhh1[r];
    }

    // layer-0 input weights (K=6) loaded once
    for (int i = tid; i < 64 * 6; i += NTHR) {
        int c = i / 6, k = i - c * 6;
        Ws6[c][k] = Wih0[((c >> 4) * HID + ub + (c & 15)) * 6 + k];
    }

    // zero h0/h1 initial + cell states (each block zeroes its 2048-float slice)
    {
        int base = bid * (NH / NBLK);
        for (int i = tid; i < NH / NBLK; i += NTHR) {
            g_h0a[base + i] = 0.0f;
            g_h1a[base + i] = 0.0f;
            g_c0[base + i]  = 0.0f;
            g_c1[base + i]  = 0.0f;
        }
    }
    grid_sync();

    #pragma unroll 1
    for (int t = 0; t < L_SEQ; ++t) {
        float* h0p = (t & 1) ? g_h0b : g_h0a;
        float* h0c = (t & 1) ? g_h0a : g_h0b;
        float* h1p = (t & 1) ? g_h1b : g_h1a;
        float* h1c = (t & 1) ? g_h1a : g_h1b;

        // ================= layer 0 =================
        {
            // stage this step's x tile (made visible by gemm's syncthreads)
            const float* xa = seq + (size_t)(t * NB + mb) * 6;
            for (int i = tid; i < 128 * 6; i += NTHR) {
                int r = i / 6, k = i - r * 6;
                Xs[r][k] = xa[r * 6 + k];
            }

            float acc[8][4] = {};
            gemm1024(h0p + mb * HID, Whh0 + wofs, acc, As, Bs, lm, lk4, lc, lkb, m0, u);

            // x projection, K = 6
            #pragma unroll
            for (int k = 0; k < 6; ++k) {
                float b0 = Ws6[u][k], b1 = Ws6[16 + u][k];
                float b2 = Ws6[32 + u][k], b3 = Ws6[48 + u][k];
                #pragma unroll
                for (int i = 0; i < 8; ++i) {
                    float a = Xs[m0 + i][k];
                    acc[i][0] += a * b0; acc[i][1] += a * b1;
                    acc[i][2] += a * b2; acc[i][3] += a * b3;
                }
            }

            #pragma unroll
            for (int i = 0; i < 8; ++i) {
                float iv = sigm(acc[i][0] + bias0[0]);
                float fv = sigm(acc[i][1] + bias0[1]);
                float gv = tanhf(acc[i][2] + bias0[2]);
                float ov = sigm(acc[i][3] + bias0[3]);
                int gi = (mb + m0 + i) * HID + ub + u;
                float c = fv * g_c0[gi] + iv * gv;
                g_c0[gi] = c;
                h0c[gi] = ov * tanhf(c);
            }
        }
        grid_sync();

        // ================= layer 1 =================
        {
            float acc[8][4] = {};
            gemm1024(h0c + mb * HID, Wih1 + wofs, acc, As, Bs, lm, lk4, lc, lkb, m0, u);
            gemm1024(h1p + mb * HID, Whh1 + wofs, acc, As, Bs, lm, lk4, lc, lkb, m0, u);

            #pragma unroll
            for (int i = 0; i < 8; ++i) {
                float iv = sigm(acc[i][0] + bias1[0]);
                float fv = sigm(acc[i][1] + bias1[1]);
                float gv = tanhf(acc[i][2] + bias1[2]);
                float ov = sigm(acc[i][3] + bias1[3]);
                int gi = (mb + m0 + i) * HID + ub + u;
                float c = fv * g_c1[gi] + iv * gv;
                g_c1[gi] = c;
                h1c[gi] = ov * tanhf(c);
            }
        }
        grid_sync();
    }

    // ---- final linear on last layer-1 output (t=511 odd -> wrote g_h1a) ----
    const float* hl = g_h1a;
    #pragma unroll 1
    for (int r = 0; r < 2; ++r) {
        int row = bid * 2 + r;
        const float* hr = hl + (size_t)row * HID;
        float s = 0.0f;
        for (int k = tid; k < HID; k += NTHR) s += hr[k] * linW[k];
        #pragma unroll
        for (int o = 16; o; o >>= 1) s += __shfl_down_sync(0xffffffffu, s, o);
        if ((tid & 31) == 0) red[tid >> 5] = s;
        __syncthreads();
        if (tid == 0) {
            float tot = red[0] + red[1] + red[2] + red[3]
                      + red[4] + red[5] + red[6] + red[7];
            out[row] = tot + linb[0];
        }
        __syncthreads();
    }
}

// ---------------------------------------------------------------------------
// kernel_launch: exactly ONE kernel node -> minimal graph, no residual driver
// upload buffer after teardown.
// ---------------------------------------------------------------------------
extern "C" void kernel_launch(void* const* d_in, const int* in_sizes, int n_in,
                              void* d_out, int out_size)
{
    (void)in_sizes; (void)n_in; (void)out_size;
    lstm_persist<<<NBLK, NTHR>>>(
        (const float*)d_in[0],                      // sequence
        (const float*)d_in[1], (const float*)d_in[2],   // W_ih_0, W_hh_0
        (const float*)d_in[3], (const float*)d_in[4],   // b_ih_0, b_hh_0
        (const float*)d_in[5], (const float*)d_in[6],   // W_ih_1, W_hh_1
        (const float*)d_in[7], (const float*)d_in[8],   // b_ih_1, b_hh_1
        (const float*)d_in[9], (const float*)d_in[10],  // lin_W, lin_b
        (float*)d_out);
}

// round 4
// speedup vs baseline: 2.3907x; 2.3907x over previous
#include <cuda_runtime.h>
#include <cuda_bf16.h>
#include <math.h>

#define HID   1024
#define NB    256
#define L_SEQ 512
#define NH    (NB * HID)
#define NBLK  128
#define NTHR  256
#define NFRAG (512 * 64 * 32)   // 512 n-groups * 64 k-tiles * 32 lanes

// packed B fragments: [0]=Whh0 hi [1]=Whh0 lo [2]=Wih1 hi [3]=Wih1 lo [4]=Whh1 hi [5]=Whh1 lo
__device__ uint2         g_Wp[6][NFRAG];
__device__ __nv_bfloat16 g_h[8][NH];     // h0a hi/lo, h0b hi/lo, h1a hi/lo, h1b hi/lo
__device__ float         g_c0[NH], g_c1[NH];
__device__ unsigned      g_count = 0, g_gen = 0;

__device__ __forceinline__ float sigm(float x){ return __fdividef(1.f, 1.f + __expf(-x)); }
__device__ __forceinline__ float ftanh(float x){ float e=__expf(2.f*x); return 1.f-__fdividef(2.f,e+1.f); }
// packed col p (0..4095) -> weight row: unit-major within 64-col slice
__device__ __forceinline__ int colmap(int p){ int s=p>>6, nl=p&63; return (nl&3)*HID + (s<<4) + (nl>>2); }
__device__ __forceinline__ unsigned pkbf(__nv_bfloat16 a,__nv_bfloat16 b){
    __nv_bfloat162 t; t.x=a; t.y=b; return *reinterpret_cast<unsigned*>(&t); }

__device__ __forceinline__ void grid_sync(){
    __syncthreads();
    if (threadIdx.x==0){
        __threadfence();
        unsigned g=*(volatile unsigned*)&g_gen;
        if (atomicAdd(&g_count,1u)==NBLK-1){ g_count=0; __threadfence(); atomicAdd(&g_gen,1u); }
        else while (*(volatile unsigned*)&g_gen==g){}
        __threadfence();
    }
    __syncthreads();
}

#define MMA(d,a,b0v,b1v) asm volatile( \
  "mma.sync.aligned.m16n8k16.row.col.f32.bf16.bf16.f32 {%0,%1,%2,%3},{%4,%5,%6,%7},{%8,%9},{%0,%1,%2,%3};" \
  : "+f"(d[0]),"+f"(d[1]),"+f"(d[2]),"+f"(d[3]) \
  : "r"(a[0]),"r"(a[1]),"r"(a[2]),"r"(a[3]),"r"(b0v),"r"(b1v))
#define LDSM4(r,addr) asm volatile( \
  "ldmatrix.sync.aligned.m8n8.x4.shared.b16 {%0,%1,%2,%3},[%4];" \
  : "=r"(r[0]),"=r"(r[1]),"=r"(r[2]),"=r"(r[3]) : "r"(addr))

// GEMM-accumulate over K=1024, block tile 128m x 64n, warp tile 64m x 16n.
__device__ __forceinline__ void gemm_k1024(
    const __nv_bfloat16* __restrict__ Ahi, const __nv_bfloat16* __restrict__ Alo,
    const uint2* __restrict__ Bhi, const uint2* __restrict__ Blo,
    int jn0, int lane, int tid, unsigned aHb, unsigned aLb,
    __nv_bfloat16 (*AsH)[40], __nv_bfloat16 (*AsL)[40], float (&acc)[4][2][4])
{
    const int srow = tid>>1, scol = (tid&1)*16;
    const __nv_bfloat16* gh = Ahi + srow*HID + scol;
    const __nv_bfloat16* gl = Alo + srow*HID + scol;
    uint4 ph0=__ldcg((const uint4*)gh),     ph1=__ldcg((const uint4*)(gh+8));
    uint4 pl0=__ldcg((const uint4*)gl),     pl1=__ldcg((const uint4*)(gl+8));

    #pragma unroll 1
    for (int k0=0; k0<HID; k0+=32){
        const int kt=k0>>4;
        uint2 bh[2][2], bl[2][2];
        #pragma unroll
        for (int h=0;h<2;++h)
            #pragma unroll
            for (int nt=0;nt<2;++nt){
                int idx=((jn0+nt)*64 + kt+h)*32 + lane;
                bh[h][nt]=Bhi[idx]; bl[h][nt]=Blo[idx];
            }
        __syncthreads();
        *(uint4*)&AsH[srow][scol]=ph0; *(uint4*)&AsH[srow][scol+8]=ph1;
        *(uint4*)&AsL[srow][scol]=pl0; *(uint4*)&AsL[srow][scol+8]=pl1;
        __syncthreads();
        if (k0+32<HID){
            ph0=__ldcg((const uint4*)(gh+k0+32)); ph1=__ldcg((const uint4*)(gh+k0+40));
            pl0=__ldcg((const uint4*)(gl+k0+32)); pl1=__ldcg((const uint4*)(gl+k0+40));
        }
        #pragma unroll
        for (int h=0;h<2;++h){
            unsigned ah[4][4], al[4][4];
            #pragma unroll
            for (int mt=0;mt<4;++mt){ LDSM4(ah[mt], aHb+mt*1280+h*32); LDSM4(al[mt], aLb+mt*1280+h*32); }
            #pragma unroll
            for (int mt=0;mt<4;++mt)
                #pragma unroll
                for (int nt=0;nt<2;++nt){
                    MMA(acc[mt][nt], ah[mt], bh[h][nt].x, bh[h][nt].y);
                    MMA(acc[mt][nt], ah[mt], bl[h][nt].x, bl[h][nt].y);
                    MMA(acc[mt][nt], al[mt], bh[h][nt].x, bh[h][nt].y);
                }
        }
    }
}

__global__ void __launch_bounds__(NTHR,1) lstm_tc(
    const float* __restrict__ seq,
    const float* __restrict__ Wih0, const float* __restrict__ Whh0,
    const float* __restrict__ bih0, const float* __restrict__ bhh0,
    const float* __restrict__ Wih1, const float* __restrict__ Whh1,
    const float* __restrict__ bih1, const float* __restrict__ bhh1,
    const float* __restrict__ linW, const float* __restrict__ linb,
    float* __restrict__ out)
{
    __shared__ __nv_bfloat16 AsH[128][40], AsL[128][40];
    __shared__ float Xs[128][6], W6s[64][6];
    __shared__ __align__(16) float biasS0[64], biasS1[64];
    __shared__ float red[8];

    const int tid=threadIdx.x, bid=blockIdx.x, lane=tid&31, w=tid>>5;
    const int s=bid>>1, mb=(bid&1)*128;        // n-slice (16 units), batch half
    const int wm=(w&1)*64, wn=(w>>1)*16;       // warp tile bases
    const int jn0=s*8+(wn>>3);
    const int gq=lane>>2, iq=lane&3, odd=iq&1;

    // ---- pack weights into B-fragment layout (once per launch) ----
    {
        const float* Wsrc[3]={Whh0,Wih1,Whh1};
        for (int f=bid*8+w; f<3*32768; f+=NBLK*8){
            int mat=f>>15, rem=f&32767, jn=rem>>6, kt=rem&63;
            int j=colmap(jn*8+(lane>>2));
            int k0=(kt<<4)+(lane&3)*2;
            const float* W=Wsrc[mat]+j*HID+k0;
            float2 w0=*(const float2*)W, w8=*(const float2*)(W+8);
            __nv_bfloat16 h0=__float2bfloat16(w0.x), h1=__float2bfloat16(w0.y);
            __nv_bfloat16 h2=__float2bfloat16(w8.x), h3=__float2bfloat16(w8.y);
            __nv_bfloat16 l0=__float2bfloat16(w0.x-__bfloat162float(h0));
            __nv_bfloat16 l1=__float2bfloat16(w0.y-__bfloat162float(h1));
            __nv_bfloat16 l2=__float2bfloat16(w8.x-__bfloat162float(h2));
            __nv_bfloat16 l3=__float2bfloat16(w8.y-__bfloat162float(h3));
            int idx=(jn*64+kt)*32+lane;
            g_Wp[mat*2  ][idx]=make_uint2(pkbf(h0,h1),pkbf(h2,h3));
            g_Wp[mat*2+1][idx]=make_uint2(pkbf(l0,l1),pkbf(l2,l3));
        }
    }
    // ---- zero initial states ----
    {
        int base=bid*(NH/NBLK); __nv_bfloat16 z=__float2bfloat16(0.f);
        for (int i=tid;i<NH/NBLK;i+=NTHR){
            g_h[0][base+i]=z; g_h[1][base+i]=z; g_h[4][base+i]=z; g_h[5][base+i]=z;
            g_c0[base+i]=0.f; g_c1[base+i]=0.f;
        }
    }
    if (tid<64){
        int j=colmap(s*64+tid);
        biasS0[tid]=bih0[j]+bhh0[j]; biasS1[tid]=bih1[j]+bhh1[j];
    }
    for (int i=tid;i<64*6;i+=NTHR){ int c=i/6,k=i-c*6; W6s[c][k]=Wih0[colmap(s*64+c)*6+k]; }
    grid_sync();

    // ldmatrix per-lane addresses (A fragment order m0-7/k0-7, m8-15/k0-7, m0-7/k8-15, m8-15/k8-15)
    const int j8=lane>>3, r8=lane&7;
    const int alr=wm+(j8&1)*8+r8, alc=(j8>>1)*8;
    unsigned aHb=(unsigned)__cvta_generic_to_shared(&AsH[alr][alc]);
    unsigned aLb=(unsigned)__cvta_generic_to_shared(&AsL[alr][alc]);

    #pragma unroll 1
    for (int t=0;t<L_SEQ;++t){
        const __nv_bfloat16 *h0pH,*h0pL,*h1pH,*h1pL; __nv_bfloat16 *h0cH,*h0cL,*h1cH,*h1cL;
        if (t&1){ h0pH=g_h[2];h0pL=g_h[3];h0cH=g_h[0];h0cL=g_h[1];
                  h1pH=g_h[6];h1pL=g_h[7];h1cH=g_h[4];h1cL=g_h[5]; }
        else    { h0pH=g_h[0];h0pL=g_h[1];h0cH=g_h[2];h0cL=g_h[3];
                  h1pH=g_h[4];h1pL=g_h[5];h1cH=g_h[6];h1cL=g_h[7]; }

        for (int layer=0;layer<2;++layer){
            float acc[4][2][4];
            #pragma unroll
            for (int a=0;a<4;++a){ acc[a][0][0]=acc[a][0][1]=acc[a][0][2]=acc[a][0][3]=0.f;
                                   acc[a][1][0]=acc[a][1][1]=acc[a][1][2]=acc[a][1][3]=0.f; }
            if (layer==0){
                const float* xa=seq+((size_t)t*NB+mb)*6;
                for (int i=tid;i<128*6;i+=NTHR){ int r=i/6,k=i-r*6; Xs[r][k]=xa[r*6+k]; }
                // Xs made visible by first __syncthreads inside gemm
                gemm_k1024(h0pH+mb*HID,h0pL+mb*HID,g_Wp[0],g_Wp[1],jn0,lane,tid,aHb,aLb,AsH,AsL,acc);
                // x projection K=6 in fragment layout
                #pragma unroll
                for (int mt=0;mt<4;++mt)
                    #pragma unroll
                    for (int nt=0;nt<2;++nt)
                        #pragma unroll
                        for (int c=0;c<4;++c){
                            int r=wm+mt*16+gq+((c>>1)<<3);
                            int nl=wn+nt*8+2*iq+(c&1);
                            float sx=0.f;
                            #pragma unroll
                            for (int k=0;k<6;++k) sx+=Xs[r][k]*W6s[nl][k];
                            acc[mt][nt][c]+=sx;
                        }
            } else {
                gemm_k1024(h0cH+mb*HID,h0cL+mb*HID,g_Wp[2],g_Wp[3],jn0,lane,tid,aHb,aLb,AsH,AsL,acc);
                gemm_k1024(h1pH+mb*HID,h1pL+mb*HID,g_Wp[4],g_Wp[5],jn0,lane,tid,aHb,aLb,AsH,AsL,acc);
            }
            // epilogue: shfl_xor(1) pairs share a unit; even lane -> row gq, odd -> row gq+8
            const float* bS=(layer==0)?biasS0:biasS1;
            float* Cst=(layer==0)?g_c0:g_c1;
            __nv_bfloat16* Hh=(layer==0)?h0cH:h1cH;
            __nv_bfloat16* Hl=(layer==0)?h0cL:h1cL;
            #pragma unroll
            for (int mt=0;mt<4;++mt)
                #pragma unroll
                for (int nt=0;nt<2;++nt){
                    float c0=acc[mt][nt][0],c1=acc[mt][nt][1],c2=acc[mt][nt][2],c3=acc[mt][nt][3];
                    float v0=__shfl_xor_sync(~0u,c0,1), v1=__shfl_xor_sync(~0u,c1,1);
                    float v2=__shfl_xor_sync(~0u,c2,1), v3=__shfl_xor_sync(~0u,c3,1);
                    float zi,zf,zg,zo; int row;
                    if(!odd){ zi=c0;zf=c1;zg=v0;zo=v1;row=gq; } else { zi=v2;zf=v3;zg=c2;zo=c3;row=gq+8; }
                    int ul=(wn>>2)+nt*2+(iq>>1);
                    float4 bb=*(const float4*)&bS[ul<<2];
                    float ii=sigm(zi+bb.x), ff=sigm(zf+bb.y), gg=ftanh(zg+bb.z), oo=sigm(zo+bb.w);
                    int m=mb+wm+mt*16+row;
                    int idx=m*HID+(s<<4)+ul;
                    float c=ff*Cst[idx]+ii*gg;
                    Cst[idx]=c;
                    float hv=oo*ftanh(c);
                    __nv_bfloat16 hh=__float2bfloat16(hv);
                    Hh[idx]=hh; Hl[idx]=__float2bfloat16(hv-__bfloat162float(hh));
                }
            grid_sync();
        }
    }

    // ---- final linear on last h1 (t=511 odd -> wrote g_h[4]/g_h[5]) ----
    #pragma unroll 1
    for (int r=0;r<2;++r){
        int row=bid*2+r;
        float ssum=0.f;
        for (int k=tid;k<HID;k+=NTHR){
            int idx=row*HID+k;
            float hv=__bfloat162float(g_h[4][idx])+__bfloat162float(g_h[5][idx]);
            ssum+=hv*linW[k];
        }
        #pragma unroll
        for (int o=16;o;o>>=1) ssum+=__shfl_down_sync(~0u,ssum,o);
        if ((tid&31)==0) red[tid>>5]=ssum;
        __syncthreads();
        if (tid==0) out[row]=red[0]+red[1]+red[2]+red[3]+red[4]+red[5]+red[6]+red[7]+linb[0];
        __syncthreads();
    }
}

extern "C" void kernel_launch(void* const* d_in, const int* in_sizes, int n_in,
                              void* d_out, int out_size)
{
    (void)in_sizes;(void)n_in;(void)out_size;
    lstm_tc<<<NBLK,NTHR>>>(
        (const float*)d_in[0],
        (const float*)d_in[1],(const float*)d_in[2],
        (const float*)d_in[3],(const float*)d_in[4],
        (const float*)d_in[5],(const float*)d_in[6],
        (const float*)d_in[7],(const float*)d_in[8],
        (const float*)d_in[9],(const float*)d_in[10],
        (float*)d_out);
}